// round 8
// baseline (speedup 1.0000x reference)
#include <cuda_runtime.h>
#include <cuda_bf16.h>
#include <math.h>
#include <stdint.h>

#define B_   2
#define CIN  64
#define H_   80
#define W_   80
#define HW   6400

// ---------------- mma.sync m16n8k16 bf16 (sm_80+ baseline) ----------------
__device__ __forceinline__ void mma16816(float* c, uint32_t a0, uint32_t a1, uint32_t a2, uint32_t a3,
                                         uint32_t b0, uint32_t b1){
  asm volatile("mma.sync.aligned.m16n8k16.row.col.f32.bf16.bf16.f32 "
    "{%0,%1,%2,%3}, {%4,%5,%6,%7}, {%8,%9}, {%0,%1,%2,%3};"
    : "+f"(c[0]), "+f"(c[1]), "+f"(c[2]), "+f"(c[3])
    : "r"(a0), "r"(a1), "r"(a2), "r"(a3), "r"(b0), "r"(b1));
}

// ---------------- scratch ----------------
__device__ __align__(16) float g_xt[B_*HW*CIN];             // fp32 NHWC for dcn gather
__device__ __align__(16) __nv_bfloat16 g_xhi[B_*HW*CIN];
__device__ __align__(16) __nv_bfloat16 g_xlo[B_*HW*CIN];
__device__ float g_y3[B_*27*HW];
__device__ float g_y5[B_*75*HW];
__device__ float g_y7[B_*147*HW];
__device__ float g_b3[32];
__device__ float g_b5[80];
__device__ float g_b7[152];
// conv weights bf16, [tap][split(hi,lo)][NP][64]
__device__ __align__(16) __nv_bfloat16 g_gw3[9*2*32*64];
__device__ __align__(16) __nv_bfloat16 g_gw5[25*2*80*64];
__device__ __align__(16) __nv_bfloat16 g_gw7[49*2*152*64];
// dcn weights bf16, [tap][split(hi,lo)][64 oc][64 c]
__device__ __align__(16) __nv_bfloat16 g_wdb3[9*2*64*64];
__device__ __align__(16) __nv_bfloat16 g_wdb5[25*2*64*64];
__device__ __align__(16) __nv_bfloat16 g_wdb7[49*2*64*64];

// ---------------- NCHW -> NHWC transpose (+ bf16 hi/lo split) ----------------
__global__ void transpose_kernel(const float* __restrict__ x, float* __restrict__ xt,
                                 __nv_bfloat16* __restrict__ xhi, __nv_bfloat16* __restrict__ xlo){
  __shared__ float s[64][33];
  int b   = blockIdx.x / 200;
  int hw0 = (blockIdx.x % 200) * 32;
  int tx = threadIdx.x & 31, ty = threadIdx.x >> 5;
  #pragma unroll
  for (int i = 0; i < 8; i++){
    int c = i*8 + ty;
    s[c][tx] = x[((size_t)(b*CIN + c))*HW + hw0 + tx];
  }
  __syncthreads();
  #pragma unroll
  for (int i = 0; i < 8; i++){
    int idx = i*256 + threadIdx.x;
    int hw = idx >> 6, c = idx & 63;
    float v = s[c][hw];
    size_t o = ((size_t)b*HW + hw0 + hw)*CIN + c;
    xt[o] = v;
    __nv_bfloat16 hi = __float2bfloat16(v);
    xhi[o] = hi;
    xlo[o] = __float2bfloat16(v - __bfloat162float(hi));
  }
}

// ---------------- merged weight packing ----------------
template<int KK, int NP>
__device__ __forceinline__ void pack_branch(const float* __restrict__ woff, const float* __restrict__ boff,
                            const float* __restrict__ wmask, const float* __restrict__ bmask,
                            const float* __restrict__ wdcn,
                            __nv_bfloat16* __restrict__ gw, float* __restrict__ bp,
                            __nv_bfloat16* __restrict__ wdb){
  int stride = gridDim.x * blockDim.x;
  int t0 = blockIdx.x*blockDim.x + threadIdx.x;
  for (int i = t0; i < KK*2*NP*64; i += stride){
    int tap = i / (2*NP*64);
    int s   = (i / (NP*64)) & 1;
    int n   = (i / 64) % NP;
    int c   = i & 63;
    float v = 0.f;
    if (n < 2*KK)      v = woff[((size_t)n*CIN + c)*KK + tap];
    else if (n < 3*KK) v = wmask[((size_t)(n-2*KK)*CIN + c)*KK + tap];
    __nv_bfloat16 hi = __float2bfloat16(v);
    gw[i] = (s == 0) ? hi : __float2bfloat16(v - __bfloat162float(hi));
  }
  for (int i = t0; i < NP; i += stride){
    float v = 0.f;
    if (i < 2*KK)      v = boff[i];
    else if (i < 3*KK) v = bmask[i-2*KK];
    bp[i] = v;
  }
  for (int i = t0; i < KK*2*64*64; i += stride){
    int tap = i / (2*4096);
    int s   = (i / 4096) & 1;
    int n   = (i / 64) % 64;
    int c   = i & 63;
    float v = wdcn[((size_t)n*64 + c)*KK + tap];
    __nv_bfloat16 hi = __float2bfloat16(v);
    wdb[i] = (s == 0) ? hi : __float2bfloat16(v - __bfloat162float(hi));
  }
}

__global__ void pack_all(const float* w_off3, const float* b_off3, const float* w_mask3, const float* b_mask3, const float* w_dcn3,
                         const float* w_off5, const float* b_off5, const float* w_mask5, const float* b_mask5, const float* w_dcn5,
                         const float* w_off7, const float* b_off7, const float* w_mask7, const float* b_mask7, const float* w_dcn7,
                         __nv_bfloat16* gw3, float* bp3, __nv_bfloat16* wdb3,
                         __nv_bfloat16* gw5, float* bp5, __nv_bfloat16* wdb5,
                         __nv_bfloat16* gw7, float* bp7, __nv_bfloat16* wdb7){
  pack_branch<49,152>(w_off7, b_off7, w_mask7, b_mask7, w_dcn7, gw7, bp7, wdb7);
  pack_branch<25,80> (w_off5, b_off5, w_mask5, b_mask5, w_dcn5, gw5, bp5, wdb5);
  pack_branch<9,32>  (w_off3, b_off3, w_mask3, b_mask3, w_dcn3, gw3, bp3, wdb3);
}

// ---------------- HMMA implicit-GEMM conv branch ----------------
template<int K, int NP>
__device__ __forceinline__ void conv_branch(char* smem,
                         const __nv_bfloat16* __restrict__ xhi, const __nv_bfloat16* __restrict__ xlo,
                         const __nv_bfloat16* __restrict__ gw, const float* __restrict__ bp,
                         float* __restrict__ y, int blk){
  constexpr int KK = K*K, PAD = K/2, Cout = 3*KK, NF = NP/8;
  constexpr int HR = 8 + K - 1, WR = 16 + K - 1;
  constexpr int PITCH = 144;
  constexpr int XS_SPLIT = HR*WR*PITCH;
  constexpr int BS_OFF   = 2*XS_SPLIT;
  constexpr int BS_SPLIT = NP*PITCH;

  char* xs = smem;
  char* Bs = smem + BS_OFF;

  const int tid  = threadIdx.x;
  const int warp = tid >> 5;
  const int lane = tid & 31;
  const int b = blk / 50;
  const int t = blk % 50;
  const int ty0 = (t / 5) * 8;
  const int tx0 = (t % 5) * 16;

  for (int i = tid; i < HR*WR*8; i += 256){
    int hp = i >> 3, c16 = i & 7;
    int gy = ty0 - PAD + hp / WR;
    int gx = tx0 - PAD + hp % WR;
    uint4 vh = make_uint4(0,0,0,0), vl = make_uint4(0,0,0,0);
    if (gy >= 0 && gy < H_ && gx >= 0 && gx < W_){
      size_t idx = ((size_t)(b*HW + gy*W_ + gx))*64 + c16*8;
      vh = *(const uint4*)(xhi + idx);
      vl = *(const uint4*)(xlo + idx);
    }
    *(uint4*)(xs + hp*PITCH + c16*16) = vh;
    *(uint4*)(xs + XS_SPLIT + hp*PITCH + c16*16) = vl;
  }

  float acc[NF][4];
  #pragma unroll
  for (int nf = 0; nf < NF; nf++){
    acc[nf][0] = acc[nf][1] = acc[nf][2] = acc[nf][3] = 0.f;
  }

  const int q  = lane & 3;
  const int r8 = lane >> 2;

  for (int tap = 0; tap < KK; tap++){
    for (int i = tid; i < 2*NP*8; i += 256){
      int s = i / (NP*8);
      int n = (i >> 3) % NP;
      int c16 = i & 7;
      uint4 v = *(const uint4*)(gw + (((size_t)tap*2 + s)*NP + n)*64 + c16*8);
      *(uint4*)(Bs + s*BS_SPLIT + n*PITCH + c16*16) = v;
    }
    __syncthreads();

    int iy = tap / K, ix = tap % K;
    const char* abase = xs + ((warp + iy)*WR + ix + r8)*PITCH + q*4;

    #pragma unroll
    for (int ks = 0; ks < 4; ks++){
      uint32_t ah0 = *(const uint32_t*)(abase + ks*32);
      uint32_t ah1 = *(const uint32_t*)(abase + 8*PITCH + ks*32);
      uint32_t ah2 = *(const uint32_t*)(abase + ks*32 + 16);
      uint32_t ah3 = *(const uint32_t*)(abase + 8*PITCH + ks*32 + 16);
      uint32_t al0 = *(const uint32_t*)(abase + XS_SPLIT + ks*32);
      uint32_t al1 = *(const uint32_t*)(abase + XS_SPLIT + 8*PITCH + ks*32);
      uint32_t al2 = *(const uint32_t*)(abase + XS_SPLIT + ks*32 + 16);
      uint32_t al3 = *(const uint32_t*)(abase + XS_SPLIT + 8*PITCH + ks*32 + 16);
      #pragma unroll
      for (int nf = 0; nf < NF; nf++){
        const char* bbase = Bs + (nf*8 + r8)*PITCH + q*4 + ks*32;
        uint32_t bh0 = *(const uint32_t*)(bbase);
        uint32_t bh1 = *(const uint32_t*)(bbase + 16);
        uint32_t bl0 = *(const uint32_t*)(bbase + BS_SPLIT);
        uint32_t bl1 = *(const uint32_t*)(bbase + BS_SPLIT + 16);
        mma16816(acc[nf], ah0, ah1, ah2, ah3, bh0, bh1);
        mma16816(acc[nf], ah0, ah1, ah2, ah3, bl0, bl1);
        mma16816(acc[nf], al0, al1, al2, al3, bh0, bh1);
      }
    }
    __syncthreads();
  }

  const int h = ty0 + warp;
  const int col0 = (lane & 3)*2;
  #pragma unroll
  for (int nf = 0; nf < NF; nf++){
    #pragma unroll
    for (int e = 0; e < 4; e++){
      int oc = nf*8 + col0 + (e & 1);
      int pc = r8 + (e >> 1)*8;
      if (oc < Cout){
        float v = acc[nf][e] + __ldg(bp + oc);
        if (oc >= 2*KK) v = 1.f/(1.f + __expf(-v));
        y[((size_t)(b*Cout + oc))*HW + h*W_ + tx0 + pc] = v;
      }
    }
  }
}

__global__ void conv_all(const __nv_bfloat16* __restrict__ xhi, const __nv_bfloat16* __restrict__ xlo,
                         const __nv_bfloat16* __restrict__ gw3, const __nv_bfloat16* __restrict__ gw5,
                         const __nv_bfloat16* __restrict__ gw7,
                         const float* __restrict__ b3, const float* __restrict__ b5, const float* __restrict__ b7,
                         float* __restrict__ y3, float* __restrict__ y5, float* __restrict__ y7){
  extern __shared__ __align__(16) char smem[];
  int blk = blockIdx.x;
  if (blk < 100)       conv_branch<7,152>(smem, xhi, xlo, gw7, b7, y7, blk);
  else if (blk < 200)  conv_branch<5,80> (smem, xhi, xlo, gw5, b5, y5, blk - 100);
  else                 conv_branch<3,32> (smem, xhi, xlo, gw3, b3, y3, blk - 200);
}

// ---------------- HMMA deformable sampling + DCN (64 px/CTA) ----------------
// smem: sampH[64][144]=9216, sampL=9216, Bs 2x9216 -> 36864
template<int K>
__device__ __forceinline__ void dcn_branch(char* smem,
                          const float* __restrict__ xt, const float* __restrict__ offm,
                          const __nv_bfloat16* __restrict__ wdb, float* __restrict__ out,
                          int outBase, int blk){
  constexpr int KK = K*K, PAD = K/2, C3 = 3*KK;
  constexpr int PITCH = 144;
  char* sampH = smem;
  char* sampL = smem + 9216;
  char* Bs    = smem + 18432;
  constexpr int BS_SPLIT = 64*PITCH;  // 9216

  const int tid  = threadIdx.x;
  const int warp = tid >> 5;
  const int lane = tid & 31;
  const int q  = lane & 3;
  const int r8 = lane >> 2;
  const int b  = blk / 100;
  const int p0 = (blk % 100) * 64;
  const int mf = warp >> 1;         // pixel group mf*16
  const int nh = warp & 1;          // n-half: nf = nh*4 + i
  const float* xb   = xt + (size_t)b*HW*CIN;
  const float* offb = offm + (size_t)b*C3*HW;

  float acc[4][4];
  #pragma unroll
  for (int i = 0; i < 4; i++) acc[i][0]=acc[i][1]=acc[i][2]=acc[i][3]=0.f;

  for (int j = 0; j < KK; j++){
    // stage dcn weights hi/lo for this tap
    for (int i = tid; i < 1024; i += 256){
      int s = i >> 9;
      int n = (i >> 3) & 63;
      int c16 = i & 7;
      uint4 v = *(const uint4*)(wdb + (((size_t)j*2 + s)*64 + n)*64 + c16*8);
      *(uint4*)(Bs + s*BS_SPLIT + n*PITCH + c16*16) = v;
    }
    // bilinear gather: warp handles pixels warp*8..+7
    int iy = j / K, ix = j - iy*K;
    #pragma unroll
    for (int r = 0; r < 8; r++){
      int p = warp*8 + r;
      int pix = p0 + p;
      int h = pix / W_, w = pix - h*W_;
      float oy = __ldg(offb + (size_t)(2*j)*HW + pix);
      float ox = __ldg(offb + (size_t)(2*j + 1)*HW + pix);
      float m  = __ldg(offb + (size_t)(2*KK + j)*HW + pix);
      float py = (float)(h - PAD + iy) + oy;
      float px = (float)(w - PAD + ix) + ox;
      float y0f = floorf(py), x0f = floorf(px);
      float wy1 = py - y0f, wx1 = px - x0f;
      float wy0 = 1.f - wy1, wx0 = 1.f - wx1;
      int y0 = (int)y0f, x0 = (int)x0f;
      bool vy0 = (y0 >= 0)  && (y0 < H_);
      bool vy1 = (y0 >= -1) && (y0 < H_ - 1);
      bool vx0 = (x0 >= 0)  && (x0 < W_);
      bool vx1 = (x0 >= -1) && (x0 < W_ - 1);
      float w00 = (vy0 && vx0) ? wy0*wx0*m : 0.f;
      float w01 = (vy0 && vx1) ? wy0*wx1*m : 0.f;
      float w10 = (vy1 && vx0) ? wy1*wx0*m : 0.f;
      float w11 = (vy1 && vx1) ? wy1*wx1*m : 0.f;
      int y0c = min(max(y0, 0), H_-1), y1c = min(max(y0 + 1, 0), H_-1);
      int x0c = min(max(x0, 0), W_-1), x1c = min(max(x0 + 1, 0), W_-1);
      int c = lane * 2;
      float2 t00 = *(const float2*)(xb + (size_t)(y0c*W_ + x0c)*CIN + c);
      float2 t01 = *(const float2*)(xb + (size_t)(y0c*W_ + x1c)*CIN + c);
      float2 t10 = *(const float2*)(xb + (size_t)(y1c*W_ + x0c)*CIN + c);
      float2 t11 = *(const float2*)(xb + (size_t)(y1c*W_ + x1c)*CIN + c);
      float vx = w00*t00.x + w01*t01.x + w10*t10.x + w11*t11.x;
      float vy = w00*t00.y + w01*t01.y + w10*t10.y + w11*t11.y;
      __nv_bfloat16 hx = __float2bfloat16(vx);
      __nv_bfloat16 hy = __float2bfloat16(vy);
      __nv_bfloat16 lx = __float2bfloat16(vx - __bfloat162float(hx));
      __nv_bfloat16 ly = __float2bfloat16(vy - __bfloat162float(hy));
      __nv_bfloat162 hv; hv.x = hx; hv.y = hy;
      __nv_bfloat162 lv; lv.x = lx; lv.y = ly;
      *(__nv_bfloat162*)(sampH + p*PITCH + lane*4) = hv;
      *(__nv_bfloat162*)(sampL + p*PITCH + lane*4) = lv;
    }
    __syncthreads();
    // 3-split mma: A = samp rows (pixels mf*16..), B = weights [oc][c]
    const char* abase = sampH + (mf*16 + r8)*PITCH + q*4;
    #pragma unroll
    for (int ks = 0; ks < 4; ks++){
      uint32_t ah0 = *(const uint32_t*)(abase + ks*32);
      uint32_t ah1 = *(const uint32_t*)(abase + 8*PITCH + ks*32);
      uint32_t ah2 = *(const uint32_t*)(abase + ks*32 + 16);
      uint32_t ah3 = *(const uint32_t*)(abase + 8*PITCH + ks*32 + 16);
      uint32_t al0 = *(const uint32_t*)(abase + 9216 + ks*32);
      uint32_t al1 = *(const uint32_t*)(abase + 9216 + 8*PITCH + ks*32);
      uint32_t al2 = *(const uint32_t*)(abase + 9216 + ks*32 + 16);
      uint32_t al3 = *(const uint32_t*)(abase + 9216 + 8*PITCH + ks*32 + 16);
      #pragma unroll
      for (int nfi = 0; nfi < 4; nfi++){
        int nf = nh*4 + nfi;
        const char* bbase = Bs + (nf*8 + r8)*PITCH + q*4 + ks*32;
        uint32_t bh0 = *(const uint32_t*)(bbase);
        uint32_t bh1 = *(const uint32_t*)(bbase + 16);
        uint32_t bl0 = *(const uint32_t*)(bbase + BS_SPLIT);
        uint32_t bl1 = *(const uint32_t*)(bbase + BS_SPLIT + 16);
        mma16816(acc[nfi], ah0, ah1, ah2, ah3, bh0, bh1);
        mma16816(acc[nfi], ah0, ah1, ah2, ah3, bl0, bl1);
        mma16816(acc[nfi], al0, al1, al2, al3, bh0, bh1);
      }
    }
    __syncthreads();
  }

  size_t base = ((size_t)b*192 + outBase)*HW;
  #pragma unroll
  for (int nfi = 0; nfi < 4; nfi++){
    int nf = nh*4 + nfi;
    #pragma unroll
    for (int e = 0; e < 4; e++){
      int oc = nf*8 + 2*q + (e & 1);
      int pix = p0 + mf*16 + r8 + (e >> 1)*8;
      out[base + (size_t)oc*HW + pix] = acc[nfi][e];
    }
  }
}

__global__ void dcn_all(const float* __restrict__ xt,
                        const float* __restrict__ y3, const float* __restrict__ y5, const float* __restrict__ y7,
                        const __nv_bfloat16* __restrict__ wdb3, const __nv_bfloat16* __restrict__ wdb5,
                        const __nv_bfloat16* __restrict__ wdb7,
                        float* __restrict__ out){
  extern __shared__ __align__(16) char smem[];
  int blk = blockIdx.x;
  if (blk < 200)      dcn_branch<7>(smem, xt, y7, wdb7, out, 128, blk);
  else if (blk < 400) dcn_branch<5>(smem, xt, y5, wdb5, out, 64,  blk - 200);
  else                dcn_branch<3>(smem, xt, y3, wdb3, out, 0,   blk - 400);
}

// ---------------- launch ----------------
extern "C" void kernel_launch(void* const* d_in, const int* in_sizes, int n_in,
                              void* d_out, int out_size){
  const float* x       = (const float*)d_in[0];
  const float* w_off3  = (const float*)d_in[1];
  const float* b_off3  = (const float*)d_in[2];
  const float* w_mask3 = (const float*)d_in[3];
  const float* b_mask3 = (const float*)d_in[4];
  const float* w_dcn3  = (const float*)d_in[5];
  const float* w_off5  = (const float*)d_in[6];
  const float* b_off5  = (const float*)d_in[7];
  const float* w_mask5 = (const float*)d_in[8];
  const float* b_mask5 = (const float*)d_in[9];
  const float* w_dcn5  = (const float*)d_in[10];
  const float* w_off7  = (const float*)d_in[11];
  const float* b_off7  = (const float*)d_in[12];
  const float* w_mask7 = (const float*)d_in[13];
  const float* b_mask7 = (const float*)d_in[14];
  const float* w_dcn7  = (const float*)d_in[15];
  float* out = (float*)d_out;

  float *xt, *y3, *y5, *y7, *b3, *b5, *b7;
  __nv_bfloat16 *xhi, *xlo, *gw3, *gw5, *gw7, *wdb3, *wdb5, *wdb7;
  cudaGetSymbolAddress((void**)&xt,  g_xt);
  cudaGetSymbolAddress((void**)&xhi, g_xhi);
  cudaGetSymbolAddress((void**)&xlo, g_xlo);
  cudaGetSymbolAddress((void**)&y3,  g_y3);
  cudaGetSymbolAddress((void**)&y5,  g_y5);
  cudaGetSymbolAddress((void**)&y7,  g_y7);
  cudaGetSymbolAddress((void**)&b3,  g_b3);
  cudaGetSymbolAddress((void**)&b5,  g_b5);
  cudaGetSymbolAddress((void**)&b7,  g_b7);
  cudaGetSymbolAddress((void**)&gw3, g_gw3);
  cudaGetSymbolAddress((void**)&gw5, g_gw5);
  cudaGetSymbolAddress((void**)&gw7, g_gw7);
  cudaGetSymbolAddress((void**)&wdb3, g_wdb3);
  cudaGetSymbolAddress((void**)&wdb5, g_wdb5);
  cudaGetSymbolAddress((void**)&wdb7, g_wdb7);

  const int smemConv = 2*14*22*144 + 2*152*144;   // 132480 (k7 worst case)
  const int smemDcn  = 9216*2 + 2*9216;           // 36864
  cudaFuncSetAttribute(conv_all, cudaFuncAttributeMaxDynamicSharedMemorySize, smemConv);
  cudaFuncSetAttribute(dcn_all,  cudaFuncAttributeMaxDynamicSharedMemorySize, smemDcn);

  transpose_kernel<<<400, 256>>>(x, xt, xhi, xlo);
  pack_all<<<256, 256>>>(w_off3, b_off3, w_mask3, b_mask3, w_dcn3,
                         w_off5, b_off5, w_mask5, b_mask5, w_dcn5,
                         w_off7, b_off7, w_mask7, b_mask7, w_dcn7,
                         gw3, b3, wdb3, gw5, b5, wdb5, gw7, b7, wdb7);

  conv_all<<<300, 256, smemConv>>>(xhi, xlo, gw3, gw5, gw7, b3, b5, b7, y3, y5, y7);
  dcn_all<<<600, 256, smemDcn>>>(xt, y3, y5, y7, wdb3, wdb5, wdb7, out);
}

// round 9
// speedup vs baseline: 1.0592x; 1.0592x over previous
#include <cuda_runtime.h>
#include <cuda_bf16.h>
#include <math.h>
#include <stdint.h>

#define B_   2
#define CIN  64
#define H_   80
#define W_   80
#define HW   6400
#define FULLM 0xFFFFFFFFu

// ---------------- mma.sync m16n8k16 bf16 (sm_80+ baseline) ----------------
__device__ __forceinline__ void mma16816(float* c, uint32_t a0, uint32_t a1, uint32_t a2, uint32_t a3,
                                         uint32_t b0, uint32_t b1){
  asm volatile("mma.sync.aligned.m16n8k16.row.col.f32.bf16.bf16.f32 "
    "{%0,%1,%2,%3}, {%4,%5,%6,%7}, {%8,%9}, {%0,%1,%2,%3};"
    : "+f"(c[0]), "+f"(c[1]), "+f"(c[2]), "+f"(c[3])
    : "r"(a0), "r"(a1), "r"(a2), "r"(a3), "r"(b0), "r"(b1));
}

// ---------------- scratch ----------------
__device__ __align__(16) float g_xt[B_*HW*CIN];
__device__ __align__(16) __nv_bfloat16 g_xhi[B_*HW*CIN];
__device__ __align__(16) __nv_bfloat16 g_xlo[B_*HW*CIN];
__device__ float g_y3[B_*27*HW];
__device__ float g_y5[B_*75*HW];
__device__ float g_y7[B_*147*HW];
__device__ float g_b3[32];
__device__ float g_b5[80];
__device__ float g_b7[152];
__device__ __align__(16) __nv_bfloat16 g_gw3[9*2*32*64];
__device__ __align__(16) __nv_bfloat16 g_gw5[25*2*80*64];
__device__ __align__(16) __nv_bfloat16 g_gw7[49*2*152*64];
__device__ __align__(16) __nv_bfloat16 g_wdb3[9*2*64*64];
__device__ __align__(16) __nv_bfloat16 g_wdb5[25*2*64*64];
__device__ __align__(16) __nv_bfloat16 g_wdb7[49*2*64*64];

// ---------------- NCHW -> NHWC transpose (+ bf16 hi/lo split) ----------------
__global__ void transpose_kernel(const float* __restrict__ x, float* __restrict__ xt,
                                 __nv_bfloat16* __restrict__ xhi, __nv_bfloat16* __restrict__ xlo){
  __shared__ float s[64][33];
  int b   = blockIdx.x / 200;
  int hw0 = (blockIdx.x % 200) * 32;
  int tx = threadIdx.x & 31, ty = threadIdx.x >> 5;
  #pragma unroll
  for (int i = 0; i < 8; i++){
    int c = i*8 + ty;
    s[c][tx] = x[((size_t)(b*CIN + c))*HW + hw0 + tx];
  }
  __syncthreads();
  #pragma unroll
  for (int i = 0; i < 8; i++){
    int idx = i*256 + threadIdx.x;
    int hw = idx >> 6, c = idx & 63;
    float v = s[c][hw];
    size_t o = ((size_t)b*HW + hw0 + hw)*CIN + c;
    xt[o] = v;
    __nv_bfloat16 hi = __float2bfloat16(v);
    xhi[o] = hi;
    xlo[o] = __float2bfloat16(v - __bfloat162float(hi));
  }
}

// ---------------- merged weight packing ----------------
template<int KK, int NP>
__device__ __forceinline__ void pack_branch(const float* __restrict__ woff, const float* __restrict__ boff,
                            const float* __restrict__ wmask, const float* __restrict__ bmask,
                            const float* __restrict__ wdcn,
                            __nv_bfloat16* __restrict__ gw, float* __restrict__ bp,
                            __nv_bfloat16* __restrict__ wdb){
  int stride = gridDim.x * blockDim.x;
  int t0 = blockIdx.x*blockDim.x + threadIdx.x;
  for (int i = t0; i < KK*2*NP*64; i += stride){
    int tap = i / (2*NP*64);
    int s   = (i / (NP*64)) & 1;
    int n   = (i / 64) % NP;
    int c   = i & 63;
    float v = 0.f;
    if (n < 2*KK)      v = woff[((size_t)n*CIN + c)*KK + tap];
    else if (n < 3*KK) v = wmask[((size_t)(n-2*KK)*CIN + c)*KK + tap];
    __nv_bfloat16 hi = __float2bfloat16(v);
    gw[i] = (s == 0) ? hi : __float2bfloat16(v - __bfloat162float(hi));
  }
  for (int i = t0; i < NP; i += stride){
    float v = 0.f;
    if (i < 2*KK)      v = boff[i];
    else if (i < 3*KK) v = bmask[i-2*KK];
    bp[i] = v;
  }
  for (int i = t0; i < KK*2*64*64; i += stride){
    int tap = i / (2*4096);
    int s   = (i / 4096) & 1;
    int n   = (i / 64) % 64;
    int c   = i & 63;
    float v = wdcn[((size_t)n*64 + c)*KK + tap];
    __nv_bfloat16 hi = __float2bfloat16(v);
    wdb[i] = (s == 0) ? hi : __float2bfloat16(v - __bfloat162float(hi));
  }
}

__global__ void pack_all(const float* w_off3, const float* b_off3, const float* w_mask3, const float* b_mask3, const float* w_dcn3,
                         const float* w_off5, const float* b_off5, const float* w_mask5, const float* b_mask5, const float* w_dcn5,
                         const float* w_off7, const float* b_off7, const float* w_mask7, const float* b_mask7, const float* w_dcn7,
                         __nv_bfloat16* gw3, float* bp3, __nv_bfloat16* wdb3,
                         __nv_bfloat16* gw5, float* bp5, __nv_bfloat16* wdb5,
                         __nv_bfloat16* gw7, float* bp7, __nv_bfloat16* wdb7){
  pack_branch<49,152>(w_off7, b_off7, w_mask7, b_mask7, w_dcn7, gw7, bp7, wdb7);
  pack_branch<25,80> (w_off5, b_off5, w_mask5, b_mask5, w_dcn5, gw5, bp5, wdb5);
  pack_branch<9,32>  (w_off3, b_off3, w_mask3, b_mask3, w_dcn3, gw3, bp3, wdb3);
}

// ---------------- HMMA implicit-GEMM conv branch ----------------
template<int K, int NP>
__device__ __forceinline__ void conv_branch(char* smem,
                         const __nv_bfloat16* __restrict__ xhi, const __nv_bfloat16* __restrict__ xlo,
                         const __nv_bfloat16* __restrict__ gw, const float* __restrict__ bp,
                         float* __restrict__ y, int blk){
  constexpr int KK = K*K, PAD = K/2, Cout = 3*KK, NF = NP/8;
  constexpr int HR = 8 + K - 1, WR = 16 + K - 1;
  constexpr int PITCH = 144;
  constexpr int XS_SPLIT = HR*WR*PITCH;
  constexpr int BS_OFF   = 2*XS_SPLIT;
  constexpr int BS_SPLIT = NP*PITCH;

  char* xs = smem;
  char* Bs = smem + BS_OFF;

  const int tid  = threadIdx.x;
  const int warp = tid >> 5;
  const int lane = tid & 31;
  const int b = blk / 50;
  const int t = blk % 50;
  const int ty0 = (t / 5) * 8;
  const int tx0 = (t % 5) * 16;

  for (int i = tid; i < HR*WR*8; i += 256){
    int hp = i >> 3, c16 = i & 7;
    int gy = ty0 - PAD + hp / WR;
    int gx = tx0 - PAD + hp % WR;
    uint4 vh = make_uint4(0,0,0,0), vl = make_uint4(0,0,0,0);
    if (gy >= 0 && gy < H_ && gx >= 0 && gx < W_){
      size_t idx = ((size_t)(b*HW + gy*W_ + gx))*64 + c16*8;
      vh = *(const uint4*)(xhi + idx);
      vl = *(const uint4*)(xlo + idx);
    }
    *(uint4*)(xs + hp*PITCH + c16*16) = vh;
    *(uint4*)(xs + XS_SPLIT + hp*PITCH + c16*16) = vl;
  }

  float acc[NF][4];
  #pragma unroll
  for (int nf = 0; nf < NF; nf++){
    acc[nf][0] = acc[nf][1] = acc[nf][2] = acc[nf][3] = 0.f;
  }

  const int q  = lane & 3;
  const int r8 = lane >> 2;

  for (int tap = 0; tap < KK; tap++){
    for (int i = tid; i < 2*NP*8; i += 256){
      int s = i / (NP*8);
      int n = (i >> 3) % NP;
      int c16 = i & 7;
      uint4 v = *(const uint4*)(gw + (((size_t)tap*2 + s)*NP + n)*64 + c16*8);
      *(uint4*)(Bs + s*BS_SPLIT + n*PITCH + c16*16) = v;
    }
    __syncthreads();

    int iy = tap / K, ix = tap % K;
    const char* abase = xs + ((warp + iy)*WR + ix + r8)*PITCH + q*4;

    #pragma unroll
    for (int ks = 0; ks < 4; ks++){
      uint32_t ah0 = *(const uint32_t*)(abase + ks*32);
      uint32_t ah1 = *(const uint32_t*)(abase + 8*PITCH + ks*32);
      uint32_t ah2 = *(const uint32_t*)(abase + ks*32 + 16);
      uint32_t ah3 = *(const uint32_t*)(abase + 8*PITCH + ks*32 + 16);
      uint32_t al0 = *(const uint32_t*)(abase + XS_SPLIT + ks*32);
      uint32_t al1 = *(const uint32_t*)(abase + XS_SPLIT + 8*PITCH + ks*32);
      uint32_t al2 = *(const uint32_t*)(abase + XS_SPLIT + ks*32 + 16);
      uint32_t al3 = *(const uint32_t*)(abase + XS_SPLIT + 8*PITCH + ks*32 + 16);
      #pragma unroll
      for (int nf = 0; nf < NF; nf++){
        const char* bbase = Bs + (nf*8 + r8)*PITCH + q*4 + ks*32;
        uint32_t bh0 = *(const uint32_t*)(bbase);
        uint32_t bh1 = *(const uint32_t*)(bbase + 16);
        uint32_t bl0 = *(const uint32_t*)(bbase + BS_SPLIT);
        uint32_t bl1 = *(const uint32_t*)(bbase + BS_SPLIT + 16);
        mma16816(acc[nf], ah0, ah1, ah2, ah3, bh0, bh1);
        mma16816(acc[nf], ah0, ah1, ah2, ah3, bl0, bl1);
        mma16816(acc[nf], al0, al1, al2, al3, bh0, bh1);
      }
    }
    __syncthreads();
  }

  const int h = ty0 + warp;
  const int col0 = (lane & 3)*2;
  #pragma unroll
  for (int nf = 0; nf < NF; nf++){
    #pragma unroll
    for (int e = 0; e < 4; e++){
      int oc = nf*8 + col0 + (e & 1);
      int pc = r8 + (e >> 1)*8;
      if (oc < Cout){
        float v = acc[nf][e] + __ldg(bp + oc);
        if (oc >= 2*KK) v = 1.f/(1.f + __expf(-v));
        y[((size_t)(b*Cout + oc))*HW + h*W_ + tx0 + pc] = v;
      }
    }
  }
}

__global__ void conv_all(const __nv_bfloat16* __restrict__ xhi, const __nv_bfloat16* __restrict__ xlo,
                         const __nv_bfloat16* __restrict__ gw3, const __nv_bfloat16* __restrict__ gw5,
                         const __nv_bfloat16* __restrict__ gw7,
                         const float* __restrict__ b3, const float* __restrict__ b5, const float* __restrict__ b7,
                         float* __restrict__ y3, float* __restrict__ y5, float* __restrict__ y7){
  extern __shared__ __align__(16) char smem[];
  int blk = blockIdx.x;
  if (blk < 100)       conv_branch<7,152>(smem, xhi, xlo, gw7, b7, y7, blk);
  else if (blk < 200)  conv_branch<5,80> (smem, xhi, xlo, gw5, b5, y5, blk - 100);
  else                 conv_branch<3,32> (smem, xhi, xlo, gw3, b3, y3, blk - 200);
}

// ---------------- HMMA deformable sampling + DCN (32 px/CTA, lane-parallel coeffs) ----------------
// smem: sampH[32][144]=4608, sampL=4608, Bs 2x9216 -> 27648
template<int K>
__device__ __forceinline__ void dcn_branch(char* smem,
                          const float* __restrict__ xt, const float* __restrict__ offm,
                          const __nv_bfloat16* __restrict__ wdb, float* __restrict__ out,
                          int outBase, int blk){
  constexpr int KK = K*K, PAD = K/2, C3 = 3*KK;
  constexpr int PITCH = 144;
  char* sampH = smem;
  char* sampL = smem + 4608;
  char* Bs    = smem + 9216;
  constexpr int BS_SPLIT = 64*PITCH;  // 9216

  const int tid  = threadIdx.x;
  const int warp = tid >> 5;
  const int lane = tid & 31;
  const int q  = lane & 3;
  const int r8 = lane >> 2;
  const int b  = blk / 200;
  const int p0 = (blk % 200) * 32;
  const int mf = warp & 1;
  const int nf0 = warp >> 1;
  const float* xb   = xt + (size_t)b*HW*CIN;
  const float* offb = offm + (size_t)b*C3*HW;

  // each lane owns pixel (lane&3) of this warp's 4 pixels for coefficient math
  const int pr    = lane & 3;
  const int mypix = p0 + warp*4 + pr;
  const int myh   = mypix / W_;
  const int myw   = mypix - myh*W_;
  const int c     = lane * 2;

  float acc[2][4];
  acc[0][0]=acc[0][1]=acc[0][2]=acc[0][3]=0.f;
  acc[1][0]=acc[1][1]=acc[1][2]=acc[1][3]=0.f;

  for (int j = 0; j < KK; j++){
    // stage dcn weights hi/lo for this tap
    for (int i = tid; i < 1024; i += 256){
      int s = i >> 9;
      int n = (i >> 3) & 63;
      int c16 = i & 7;
      uint4 v = *(const uint4*)(wdb + (((size_t)j*2 + s)*64 + n)*64 + c16*8);
      *(uint4*)(Bs + s*BS_SPLIT + n*PITCH + c16*16) = v;
    }
    // ---- coefficients: computed once per pixel, in parallel across lanes ----
    int iy = j / K, ix = j - iy*K;
    float oy = __ldg(offb + (size_t)(2*j)*HW + mypix);
    float ox = __ldg(offb + (size_t)(2*j + 1)*HW + mypix);
    float m  = __ldg(offb + (size_t)(2*KK + j)*HW + mypix);
    float py = (float)(myh - PAD + iy) + oy;
    float px = (float)(myw - PAD + ix) + ox;
    float y0f = floorf(py), x0f = floorf(px);
    float wy1 = py - y0f, wx1 = px - x0f;
    float wy0 = 1.f - wy1, wx0 = 1.f - wx1;
    int y0 = (int)y0f, x0 = (int)x0f;
    bool vy0 = (y0 >= 0)  && (y0 < H_);
    bool vy1 = (y0 >= -1) && (y0 < H_ - 1);
    bool vx0 = (x0 >= 0)  && (x0 < W_);
    bool vx1 = (x0 >= -1) && (x0 < W_ - 1);
    float w00 = (vy0 && vx0) ? wy0*wx0*m : 0.f;
    float w01 = (vy0 && vx1) ? wy0*wx1*m : 0.f;
    float w10 = (vy1 && vx0) ? wy1*wx0*m : 0.f;
    float w11 = (vy1 && vx1) ? wy1*wx1*m : 0.f;
    int y0c = min(max(y0, 0), H_-1), y1c = min(max(y0 + 1, 0), H_-1);
    int x0c = min(max(x0, 0), W_-1), x1c = min(max(x0 + 1, 0), W_-1);
    int o00 = y0c*W_ + x0c, o01 = y0c*W_ + x1c;
    int o10 = y1c*W_ + x0c, o11 = y1c*W_ + x1c;

    // ---- gather: 4 pixels, coeffs shuffled from owning lane ----
    #pragma unroll
    for (int r = 0; r < 4; r++){
      float W00 = __shfl_sync(FULLM, w00, r);
      float W01 = __shfl_sync(FULLM, w01, r);
      float W10 = __shfl_sync(FULLM, w10, r);
      float W11 = __shfl_sync(FULLM, w11, r);
      int O00 = __shfl_sync(FULLM, o00, r);
      int O01 = __shfl_sync(FULLM, o01, r);
      int O10 = __shfl_sync(FULLM, o10, r);
      int O11 = __shfl_sync(FULLM, o11, r);
      float2 t00 = *(const float2*)(xb + (size_t)O00*CIN + c);
      float2 t01 = *(const float2*)(xb + (size_t)O01*CIN + c);
      float2 t10 = *(const float2*)(xb + (size_t)O10*CIN + c);
      float2 t11 = *(const float2*)(xb + (size_t)O11*CIN + c);
      float vx = W00*t00.x + W01*t01.x + W10*t10.x + W11*t11.x;
      float vy = W00*t00.y + W01*t01.y + W10*t10.y + W11*t11.y;
      __nv_bfloat16 hx = __float2bfloat16(vx);
      __nv_bfloat16 hy = __float2bfloat16(vy);
      __nv_bfloat16 lx = __float2bfloat16(vx - __bfloat162float(hx));
      __nv_bfloat16 ly = __float2bfloat16(vy - __bfloat162float(hy));
      __nv_bfloat162 hv; hv.x = hx; hv.y = hy;
      __nv_bfloat162 lv; lv.x = lx; lv.y = ly;
      int p = warp*4 + r;
      *(__nv_bfloat162*)(sampH + p*PITCH + lane*4) = hv;
      *(__nv_bfloat162*)(sampL + p*PITCH + lane*4) = lv;
    }
    __syncthreads();
    // ---- 3-split mma ----
    const char* abase = sampH + (mf*16 + r8)*PITCH + q*4;
    #pragma unroll
    for (int ks = 0; ks < 4; ks++){
      uint32_t ah0 = *(const uint32_t*)(abase + ks*32);
      uint32_t ah1 = *(const uint32_t*)(abase + 8*PITCH + ks*32);
      uint32_t ah2 = *(const uint32_t*)(abase + ks*32 + 16);
      uint32_t ah3 = *(const uint32_t*)(abase + 8*PITCH + ks*32 + 16);
      uint32_t al0 = *(const uint32_t*)(abase + 4608 + ks*32);
      uint32_t al1 = *(const uint32_t*)(abase + 4608 + 8*PITCH + ks*32);
      uint32_t al2 = *(const uint32_t*)(abase + 4608 + ks*32 + 16);
      uint32_t al3 = *(const uint32_t*)(abase + 4608 + 8*PITCH + ks*32 + 16);
      #pragma unroll
      for (int nfi = 0; nfi < 2; nfi++){
        int nf = nf0 + nfi*4;
        const char* bbase = Bs + (nf*8 + r8)*PITCH + q*4 + ks*32;
        uint32_t bh0 = *(const uint32_t*)(bbase);
        uint32_t bh1 = *(const uint32_t*)(bbase + 16);
        uint32_t bl0 = *(const uint32_t*)(bbase + BS_SPLIT);
        uint32_t bl1 = *(const uint32_t*)(bbase + BS_SPLIT + 16);
        mma16816(acc[nfi], ah0, ah1, ah2, ah3, bh0, bh1);
        mma16816(acc[nfi], ah0, ah1, ah2, ah3, bl0, bl1);
        mma16816(acc[nfi], al0, al1, al2, al3, bh0, bh1);
      }
    }
    __syncthreads();
  }

  size_t base = ((size_t)b*192 + outBase)*HW;
  #pragma unroll
  for (int nfi = 0; nfi < 2; nfi++){
    int nf = nf0 + nfi*4;
    #pragma unroll
    for (int e = 0; e < 4; e++){
      int oc = nf*8 + 2*q + (e & 1);
      int pix = p0 + mf*16 + r8 + (e >> 1)*8;
      out[base + (size_t)oc*HW + pix] = acc[nfi][e];
    }
  }
}

__global__ void dcn_all(const float* __restrict__ xt,
                        const float* __restrict__ y3, const float* __restrict__ y5, const float* __restrict__ y7,
                        const __nv_bfloat16* __restrict__ wdb3, const __nv_bfloat16* __restrict__ wdb5,
                        const __nv_bfloat16* __restrict__ wdb7,
                        float* __restrict__ out){
  extern __shared__ __align__(16) char smem[];
  int blk = blockIdx.x;
  if (blk < 400)      dcn_branch<7>(smem, xt, y7, wdb7, out, 128, blk);
  else if (blk < 800) dcn_branch<5>(smem, xt, y5, wdb5, out, 64,  blk - 400);
  else                dcn_branch<3>(smem, xt, y3, wdb3, out, 0,   blk - 800);
}

// ---------------- launch ----------------
extern "C" void kernel_launch(void* const* d_in, const int* in_sizes, int n_in,
                              void* d_out, int out_size){
  const float* x       = (const float*)d_in[0];
  const float* w_off3  = (const float*)d_in[1];
  const float* b_off3  = (const float*)d_in[2];
  const float* w_mask3 = (const float*)d_in[3];
  const float* b_mask3 = (const float*)d_in[4];
  const float* w_dcn3  = (const float*)d_in[5];
  const float* w_off5  = (const float*)d_in[6];
  const float* b_off5  = (const float*)d_in[7];
  const float* w_mask5 = (const float*)d_in[8];
  const float* b_mask5 = (const float*)d_in[9];
  const float* w_dcn5  = (const float*)d_in[10];
  const float* w_off7  = (const float*)d_in[11];
  const float* b_off7  = (const float*)d_in[12];
  const float* w_mask7 = (const float*)d_in[13];
  const float* b_mask7 = (const float*)d_in[14];
  const float* w_dcn7  = (const float*)d_in[15];
  float* out = (float*)d_out;

  float *xt, *y3, *y5, *y7, *b3, *b5, *b7;
  __nv_bfloat16 *xhi, *xlo, *gw3, *gw5, *gw7, *wdb3, *wdb5, *wdb7;
  cudaGetSymbolAddress((void**)&xt,  g_xt);
  cudaGetSymbolAddress((void**)&xhi, g_xhi);
  cudaGetSymbolAddress((void**)&xlo, g_xlo);
  cudaGetSymbolAddress((void**)&y3,  g_y3);
  cudaGetSymbolAddress((void**)&y5,  g_y5);
  cudaGetSymbolAddress((void**)&y7,  g_y7);
  cudaGetSymbolAddress((void**)&b3,  g_b3);
  cudaGetSymbolAddress((void**)&b5,  g_b5);
  cudaGetSymbolAddress((void**)&b7,  g_b7);
  cudaGetSymbolAddress((void**)&gw3, g_gw3);
  cudaGetSymbolAddress((void**)&gw5, g_gw5);
  cudaGetSymbolAddress((void**)&gw7, g_gw7);
  cudaGetSymbolAddress((void**)&wdb3, g_wdb3);
  cudaGetSymbolAddress((void**)&wdb5, g_wdb5);
  cudaGetSymbolAddress((void**)&wdb7, g_wdb7);

  const int smemConv = 2*14*22*144 + 2*152*144;   // 132480 (k7 worst case)
  const int smemDcn  = 4608*2 + 2*9216;           // 27648
  cudaFuncSetAttribute(conv_all, cudaFuncAttributeMaxDynamicSharedMemorySize, smemConv);
  cudaFuncSetAttribute(dcn_all,  cudaFuncAttributeMaxDynamicSharedMemorySize, smemDcn);

  transpose_kernel<<<400, 256>>>(x, xt, xhi, xlo);
  pack_all<<<256, 256>>>(w_off3, b_off3, w_mask3, b_mask3, w_dcn3,
                         w_off5, b_off5, w_mask5, b_mask5, w_dcn5,
                         w_off7, b_off7, w_mask7, b_mask7, w_dcn7,
                         gw3, b3, wdb3, gw5, b5, wdb5, gw7, b7, wdb7);

  conv_all<<<300, 256, smemConv>>>(xhi, xlo, gw3, gw5, gw7, b3, b5, b7, y3, y5, y7);
  dcn_all<<<1200, 256, smemDcn>>>(xt, y3, y5, y7, wdb3, wdb5, wdb7, out);
}

// round 10
// speedup vs baseline: 1.1943x; 1.1275x over previous
#include <cuda_runtime.h>
#include <cuda_bf16.h>
#include <math.h>
#include <stdint.h>

#define B_   2
#define CIN  64
#define H_   80
#define W_   80
#define HW   6400
#define FULLM 0xFFFFFFFFu

// ---------------- mma.sync m16n8k16 bf16 + ldmatrix (sm_75+/80+ baseline) ----------------
__device__ __forceinline__ void mma16816(float* c, uint32_t a0, uint32_t a1, uint32_t a2, uint32_t a3,
                                         uint32_t b0, uint32_t b1){
  asm volatile("mma.sync.aligned.m16n8k16.row.col.f32.bf16.bf16.f32 "
    "{%0,%1,%2,%3}, {%4,%5,%6,%7}, {%8,%9}, {%0,%1,%2,%3};"
    : "+f"(c[0]), "+f"(c[1]), "+f"(c[2]), "+f"(c[3])
    : "r"(a0), "r"(a1), "r"(a2), "r"(a3), "r"(b0), "r"(b1));
}
__device__ __forceinline__ void ldmx4(uint32_t& r0, uint32_t& r1, uint32_t& r2, uint32_t& r3, uint32_t addr){
  asm volatile("ldmatrix.sync.aligned.m8n8.x4.shared.b16 {%0,%1,%2,%3}, [%4];"
    : "=r"(r0), "=r"(r1), "=r"(r2), "=r"(r3) : "r"(addr));
}
__device__ __forceinline__ void ldmx2(uint32_t& r0, uint32_t& r1, uint32_t addr){
  asm volatile("ldmatrix.sync.aligned.m8n8.x2.shared.b16 {%0,%1}, [%2];"
    : "=r"(r0), "=r"(r1) : "r"(addr));
}

// ---------------- scratch ----------------
__device__ __align__(16) float g_xt[B_*HW*CIN];
__device__ __align__(16) __nv_bfloat16 g_xhi[B_*HW*CIN];
__device__ __align__(16) __nv_bfloat16 g_xlo[B_*HW*CIN];
__device__ float g_y3[B_*27*HW];
__device__ float g_y5[B_*75*HW];
__device__ float g_y7a[B_*147*HW];
__device__ float g_y7b[B_*147*HW];
__device__ float g_b3[32];
__device__ float g_b5[80];
__device__ float g_b7[152];
__device__ __align__(16) __nv_bfloat16 g_gw3[9*2*32*64];
__device__ __align__(16) __nv_bfloat16 g_gw5[25*2*80*64];
__device__ __align__(16) __nv_bfloat16 g_gw7[49*2*152*64];
__device__ __align__(16) __nv_bfloat16 g_wdb3[9*2*64*64];
__device__ __align__(16) __nv_bfloat16 g_wdb5[25*2*64*64];
__device__ __align__(16) __nv_bfloat16 g_wdb7[49*2*64*64];

// ---------------- NCHW -> NHWC transpose (+ bf16 hi/lo split) ----------------
__global__ void transpose_kernel(const float* __restrict__ x, float* __restrict__ xt,
                                 __nv_bfloat16* __restrict__ xhi, __nv_bfloat16* __restrict__ xlo){
  __shared__ float s[64][33];
  int b   = blockIdx.x / 200;
  int hw0 = (blockIdx.x % 200) * 32;
  int tx = threadIdx.x & 31, ty = threadIdx.x >> 5;
  #pragma unroll
  for (int i = 0; i < 8; i++){
    int c = i*8 + ty;
    s[c][tx] = x[((size_t)(b*CIN + c))*HW + hw0 + tx];
  }
  __syncthreads();
  #pragma unroll
  for (int i = 0; i < 8; i++){
    int idx = i*256 + threadIdx.x;
    int hw = idx >> 6, c = idx & 63;
    float v = s[c][hw];
    size_t o = ((size_t)b*HW + hw0 + hw)*CIN + c;
    xt[o] = v;
    __nv_bfloat16 hi = __float2bfloat16(v);
    xhi[o] = hi;
    xlo[o] = __float2bfloat16(v - __bfloat162float(hi));
  }
}

// ---------------- merged weight packing ----------------
template<int KK, int NP>
__device__ __forceinline__ void pack_branch(const float* __restrict__ woff, const float* __restrict__ boff,
                            const float* __restrict__ wmask, const float* __restrict__ bmask,
                            const float* __restrict__ wdcn,
                            __nv_bfloat16* __restrict__ gw, float* __restrict__ bp,
                            __nv_bfloat16* __restrict__ wdb){
  int stride = gridDim.x * blockDim.x;
  int t0 = blockIdx.x*blockDim.x + threadIdx.x;
  for (int i = t0; i < KK*2*NP*64; i += stride){
    int tap = i / (2*NP*64);
    int s   = (i / (NP*64)) & 1;
    int n   = (i / 64) % NP;
    int c   = i & 63;
    float v = 0.f;
    if (n < 2*KK)      v = woff[((size_t)n*CIN + c)*KK + tap];
    else if (n < 3*KK) v = wmask[((size_t)(n-2*KK)*CIN + c)*KK + tap];
    __nv_bfloat16 hi = __float2bfloat16(v);
    gw[i] = (s == 0) ? hi : __float2bfloat16(v - __bfloat162float(hi));
  }
  for (int i = t0; i < NP; i += stride){
    float v = 0.f;
    if (i < 2*KK)      v = boff[i];
    else if (i < 3*KK) v = bmask[i-2*KK];
    bp[i] = v;
  }
  for (int i = t0; i < KK*2*64*64; i += stride){
    int tap = i / (2*4096);
    int s   = (i / 4096) & 1;
    int n   = (i / 64) % 64;
    int c   = i & 63;
    float v = wdcn[((size_t)n*64 + c)*KK + tap];
    __nv_bfloat16 hi = __float2bfloat16(v);
    wdb[i] = (s == 0) ? hi : __float2bfloat16(v - __bfloat162float(hi));
  }
}

__global__ void pack_all(const float* w_off3, const float* b_off3, const float* w_mask3, const float* b_mask3, const float* w_dcn3,
                         const float* w_off5, const float* b_off5, const float* w_mask5, const float* b_mask5, const float* w_dcn5,
                         const float* w_off7, const float* b_off7, const float* w_mask7, const float* b_mask7, const float* w_dcn7,
                         __nv_bfloat16* gw3, float* bp3, __nv_bfloat16* wdb3,
                         __nv_bfloat16* gw5, float* bp5, __nv_bfloat16* wdb5,
                         __nv_bfloat16* gw7, float* bp7, __nv_bfloat16* wdb7){
  pack_branch<49,152>(w_off7, b_off7, w_mask7, b_mask7, w_dcn7, gw7, bp7, wdb7);
  pack_branch<25,80> (w_off5, b_off5, w_mask5, b_mask5, w_dcn5, gw5, bp5, wdb5);
  pack_branch<9,32>  (w_off3, b_off3, w_mask3, b_mask3, w_dcn3, gw3, bp3, wdb3);
}

// ---------------- HMMA implicit-GEMM conv branch (tap range, optional epilogue) ----------------
template<int K, int NP, bool EPI>
__device__ __forceinline__ void conv_branch(char* smem,
                         const __nv_bfloat16* __restrict__ xhi, const __nv_bfloat16* __restrict__ xlo,
                         const __nv_bfloat16* __restrict__ gw, const float* __restrict__ bp,
                         float* __restrict__ y, int blk, int tap0, int tapN){
  constexpr int KK = K*K, PAD = K/2, Cout = 3*KK, NF = NP/8;
  constexpr int HR = 8 + K - 1, WR = 16 + K - 1;
  constexpr int PITCH = 144;
  constexpr int XS_SPLIT = HR*WR*PITCH;
  constexpr int BS_OFF   = 2*XS_SPLIT;
  constexpr int BS_SPLIT = NP*PITCH;

  char* xs = smem;
  char* Bs = smem + BS_OFF;

  const int tid  = threadIdx.x;
  const int warp = tid >> 5;
  const int lane = tid & 31;
  const int b = blk / 50;
  const int t = blk % 50;
  const int ty0 = (t / 5) * 8;
  const int tx0 = (t % 5) * 16;

  for (int i = tid; i < HR*WR*8; i += 256){
    int hp = i >> 3, c16 = i & 7;
    int gy = ty0 - PAD + hp / WR;
    int gx = tx0 - PAD + hp % WR;
    uint4 vh = make_uint4(0,0,0,0), vl = make_uint4(0,0,0,0);
    if (gy >= 0 && gy < H_ && gx >= 0 && gx < W_){
      size_t idx = ((size_t)(b*HW + gy*W_ + gx))*64 + c16*8;
      vh = *(const uint4*)(xhi + idx);
      vl = *(const uint4*)(xlo + idx);
    }
    *(uint4*)(xs + hp*PITCH + c16*16) = vh;
    *(uint4*)(xs + XS_SPLIT + hp*PITCH + c16*16) = vl;
  }

  float acc[NF][4];
  #pragma unroll
  for (int nf = 0; nf < NF; nf++){
    acc[nf][0] = acc[nf][1] = acc[nf][2] = acc[nf][3] = 0.f;
  }

  const int q  = lane & 3;
  const int r8 = lane >> 2;

  for (int tap = tap0; tap < tapN; tap++){
    for (int i = tid; i < 2*NP*8; i += 256){
      int s = i / (NP*8);
      int n = (i >> 3) % NP;
      int c16 = i & 7;
      uint4 v = *(const uint4*)(gw + (((size_t)tap*2 + s)*NP + n)*64 + c16*8);
      *(uint4*)(Bs + s*BS_SPLIT + n*PITCH + c16*16) = v;
    }
    __syncthreads();

    int iy = tap / K, ix = tap % K;
    const char* abase = xs + ((warp + iy)*WR + ix + r8)*PITCH + q*4;

    #pragma unroll
    for (int ks = 0; ks < 4; ks++){
      uint32_t ah0 = *(const uint32_t*)(abase + ks*32);
      uint32_t ah1 = *(const uint32_t*)(abase + 8*PITCH + ks*32);
      uint32_t ah2 = *(const uint32_t*)(abase + ks*32 + 16);
      uint32_t ah3 = *(const uint32_t*)(abase + 8*PITCH + ks*32 + 16);
      uint32_t al0 = *(const uint32_t*)(abase + XS_SPLIT + ks*32);
      uint32_t al1 = *(const uint32_t*)(abase + XS_SPLIT + 8*PITCH + ks*32);
      uint32_t al2 = *(const uint32_t*)(abase + XS_SPLIT + ks*32 + 16);
      uint32_t al3 = *(const uint32_t*)(abase + XS_SPLIT + 8*PITCH + ks*32 + 16);
      #pragma unroll
      for (int nf = 0; nf < NF; nf++){
        const char* bbase = Bs + (nf*8 + r8)*PITCH + q*4 + ks*32;
        uint32_t bh0 = *(const uint32_t*)(bbase);
        uint32_t bh1 = *(const uint32_t*)(bbase + 16);
        uint32_t bl0 = *(const uint32_t*)(bbase + BS_SPLIT);
        uint32_t bl1 = *(const uint32_t*)(bbase + BS_SPLIT + 16);
        mma16816(acc[nf], ah0, ah1, ah2, ah3, bh0, bh1);
        mma16816(acc[nf], ah0, ah1, ah2, ah3, bl0, bl1);
        mma16816(acc[nf], al0, al1, al2, al3, bh0, bh1);
      }
    }
    __syncthreads();
  }

  const int h = ty0 + warp;
  const int col0 = (lane & 3)*2;
  #pragma unroll
  for (int nf = 0; nf < NF; nf++){
    #pragma unroll
    for (int e = 0; e < 4; e++){
      int oc = nf*8 + col0 + (e & 1);
      int pc = r8 + (e >> 1)*8;
      if (oc < Cout){
        float v = acc[nf][e];
        if (EPI){
          v += __ldg(bp + oc);
          if (oc >= 2*KK) v = 1.f/(1.f + __expf(-v));
        }
        y[((size_t)(b*Cout + oc))*HW + h*W_ + tx0 + pc] = v;
      }
    }
  }
}

// merged conv: 400 blocks (k7 split into two tap halves, raw partials)
__global__ void conv_all(const __nv_bfloat16* __restrict__ xhi, const __nv_bfloat16* __restrict__ xlo,
                         const __nv_bfloat16* __restrict__ gw3, const __nv_bfloat16* __restrict__ gw5,
                         const __nv_bfloat16* __restrict__ gw7,
                         const float* __restrict__ b3, const float* __restrict__ b5, const float* __restrict__ b7,
                         float* __restrict__ y3, float* __restrict__ y5,
                         float* __restrict__ y7a, float* __restrict__ y7b){
  extern __shared__ __align__(16) char smem[];
  int blk = blockIdx.x;
  if (blk < 100)       conv_branch<7,152,false>(smem, xhi, xlo, gw7, b7, y7a, blk,       0, 25);
  else if (blk < 200)  conv_branch<7,152,false>(smem, xhi, xlo, gw7, b7, y7b, blk - 100, 25, 49);
  else if (blk < 300)  conv_branch<5,80,true>  (smem, xhi, xlo, gw5, b5, y5,  blk - 200, 0, 25);
  else                 conv_branch<3,32,true>  (smem, xhi, xlo, gw3, b3, y3,  blk - 300, 0, 9);
}

// ---------------- HMMA deformable sampling + DCN (32 px/CTA, ldmatrix frags) ----------------
// smem: sampH[32][144]=4608, sampL=4608, Bs 2x9216 -> 27648
template<int K, bool MERGE>
__device__ __forceinline__ void dcn_branch(char* smem,
                          const float* __restrict__ xt,
                          const float* __restrict__ offm, const float* __restrict__ offm2,
                          const float* __restrict__ bp,
                          const __nv_bfloat16* __restrict__ wdb, float* __restrict__ out,
                          int outBase, int blk){
  constexpr int KK = K*K, PAD = K/2, C3 = 3*KK;
  constexpr int PITCH = 144;
  char* sampH = smem;
  char* sampL = smem + 4608;
  char* Bs    = smem + 9216;
  constexpr int BS_SPLIT = 64*PITCH;  // 9216

  const int tid  = threadIdx.x;
  const int warp = tid >> 5;
  const int lane = tid & 31;
  const int b  = blk / 200;
  const int p0 = (blk % 200) * 32;
  const int mf = warp & 1;
  const int nf0 = warp >> 1;
  const float* xb    = xt + (size_t)b*HW*CIN;
  const float* offb  = offm + (size_t)b*C3*HW;
  const float* offb2 = MERGE ? (offm2 + (size_t)b*C3*HW) : (const float*)0;

  // coeff owner: lane owns pixel (lane&3) of this warp's 4
  const int pr    = lane & 3;
  const int mypix = p0 + warp*4 + pr;
  const int myh   = mypix / W_;
  const int myw   = mypix - myh*W_;
  // gather lanes: pg = pixel subgroup, cq = 4 channels
  const int pg = lane >> 4;
  const int cq = (lane & 15) * 4;

  // hoisted ldmatrix addresses (constant across taps)
  const uint32_t sBaseH = (uint32_t)__cvta_generic_to_shared(sampH);
  const uint32_t sBaseB = (uint32_t)__cvta_generic_to_shared(Bs);
  const uint32_t aH = sBaseH + (mf*16 + (lane & 15))*PITCH + ((lane >> 4) << 4);
  const uint32_t aL = aH + 4608;
  const uint32_t bRowOff = (lane & 7)*PITCH + (((lane >> 3) & 1) << 4);
  const uint32_t bH0 = sBaseB + (nf0*8)*PITCH + bRowOff;
  const uint32_t bH1 = bH0 + 32*PITCH;
  const uint32_t bL0 = bH0 + BS_SPLIT;
  const uint32_t bL1 = bH1 + BS_SPLIT;

  float acc[2][4];
  acc[0][0]=acc[0][1]=acc[0][2]=acc[0][3]=0.f;
  acc[1][0]=acc[1][1]=acc[1][2]=acc[1][3]=0.f;

  for (int j = 0; j < KK; j++){
    // stage dcn weights hi/lo for this tap
    for (int i = tid; i < 1024; i += 256){
      int s = i >> 9;
      int n = (i >> 3) & 63;
      int c16 = i & 7;
      uint4 v = *(const uint4*)(wdb + (((size_t)j*2 + s)*64 + n)*64 + c16*8);
      *(uint4*)(Bs + s*BS_SPLIT + n*PITCH + c16*16) = v;
    }
    // ---- coefficients (lane-parallel, one pixel per lane) ----
    int iy = j / K, ix = j - iy*K;
    float oy = __ldg(offb + (size_t)(2*j)*HW + mypix);
    float ox = __ldg(offb + (size_t)(2*j + 1)*HW + mypix);
    float m  = __ldg(offb + (size_t)(2*KK + j)*HW + mypix);
    if (MERGE){
      oy += __ldg(offb2 + (size_t)(2*j)*HW + mypix)     + __ldg(bp + 2*j);
      ox += __ldg(offb2 + (size_t)(2*j + 1)*HW + mypix) + __ldg(bp + 2*j + 1);
      m  += __ldg(offb2 + (size_t)(2*KK + j)*HW + mypix) + __ldg(bp + 2*KK + j);
      m = 1.f/(1.f + __expf(-m));
    }
    float py = (float)(myh - PAD + iy) + oy;
    float px = (float)(myw - PAD + ix) + ox;
    float y0f = floorf(py), x0f = floorf(px);
    float wy1 = py - y0f, wx1 = px - x0f;
    float wy0 = 1.f - wy1, wx0 = 1.f - wx1;
    int y0 = (int)y0f, x0 = (int)x0f;
    bool vy0 = (y0 >= 0)  && (y0 < H_);
    bool vy1 = (y0 >= -1) && (y0 < H_ - 1);
    bool vx0 = (x0 >= 0)  && (x0 < W_);
    bool vx1 = (x0 >= -1) && (x0 < W_ - 1);
    float w00 = (vy0 && vx0) ? wy0*wx0*m : 0.f;
    float w01 = (vy0 && vx1) ? wy0*wx1*m : 0.f;
    float w10 = (vy1 && vx0) ? wy1*wx0*m : 0.f;
    float w11 = (vy1 && vx1) ? wy1*wx1*m : 0.f;
    int y0c = min(max(y0, 0), H_-1), y1c = min(max(y0 + 1, 0), H_-1);
    int x0c = min(max(x0, 0), W_-1), x1c = min(max(x0 + 1, 0), W_-1);
    int o00 = y0c*W_ + x0c, o01 = y0c*W_ + x1c;
    int o10 = y1c*W_ + x0c, o11 = y1c*W_ + x1c;

    // ---- gather: 2 rounds x 2 pixels, float4 per lane (16 lanes per pixel) ----
    #pragma unroll
    for (int r = 0; r < 2; r++){
      int p = r*2 + pg;
      float W00 = __shfl_sync(FULLM, w00, p);
      float W01 = __shfl_sync(FULLM, w01, p);
      float W10 = __shfl_sync(FULLM, w10, p);
      float W11 = __shfl_sync(FULLM, w11, p);
      int O00 = __shfl_sync(FULLM, o00, p);
      int O01 = __shfl_sync(FULLM, o01, p);
      int O10 = __shfl_sync(FULLM, o10, p);
      int O11 = __shfl_sync(FULLM, o11, p);
      float4 t00 = *(const float4*)(xb + (size_t)O00*CIN + cq);
      float4 t01 = *(const float4*)(xb + (size_t)O01*CIN + cq);
      float4 t10 = *(const float4*)(xb + (size_t)O10*CIN + cq);
      float4 t11 = *(const float4*)(xb + (size_t)O11*CIN + cq);
      float v0 = W00*t00.x + W01*t01.x + W10*t10.x + W11*t11.x;
      float v1 = W00*t00.y + W01*t01.y + W10*t10.y + W11*t11.y;
      float v2 = W00*t00.z + W01*t01.z + W10*t10.z + W11*t11.z;
      float v3 = W00*t00.w + W01*t01.w + W10*t10.w + W11*t11.w;
      __nv_bfloat16 h0 = __float2bfloat16(v0), h1 = __float2bfloat16(v1);
      __nv_bfloat16 h2 = __float2bfloat16(v2), h3 = __float2bfloat16(v3);
      __nv_bfloat16 l0 = __float2bfloat16(v0 - __bfloat162float(h0));
      __nv_bfloat16 l1 = __float2bfloat16(v1 - __bfloat162float(h1));
      __nv_bfloat16 l2 = __float2bfloat16(v2 - __bfloat162float(h2));
      __nv_bfloat16 l3 = __float2bfloat16(v3 - __bfloat162float(h3));
      uint2 hv, lv;
      hv.x = ((uint32_t)__bfloat16_as_ushort(h1) << 16) | __bfloat16_as_ushort(h0);
      hv.y = ((uint32_t)__bfloat16_as_ushort(h3) << 16) | __bfloat16_as_ushort(h2);
      lv.x = ((uint32_t)__bfloat16_as_ushort(l1) << 16) | __bfloat16_as_ushort(l0);
      lv.y = ((uint32_t)__bfloat16_as_ushort(l3) << 16) | __bfloat16_as_ushort(l2);
      int pp = warp*4 + p;
      *(uint2*)(sampH + pp*PITCH + (lane & 15)*8) = hv;
      *(uint2*)(sampL + pp*PITCH + (lane & 15)*8) = lv;
    }
    __syncthreads();
    // ---- 3-split mma via ldmatrix ----
    #pragma unroll
    for (int ks = 0; ks < 4; ks++){
      uint32_t ah0, ah1, ah2, ah3, al0, al1, al2, al3;
      ldmx4(ah0, ah1, ah2, ah3, aH + ks*32);
      ldmx4(al0, al1, al2, al3, aL + ks*32);
      uint32_t b00, b01, b10, b11, c00, c01, c10, c11;
      ldmx2(b00, b01, bH0 + ks*32);
      ldmx2(b10, b11, bH1 + ks*32);
      ldmx2(c00, c01, bL0 + ks*32);
      ldmx2(c10, c11, bL1 + ks*32);
      mma16816(acc[0], ah0, ah1, ah2, ah3, b00, b01);
      mma16816(acc[0], ah0, ah1, ah2, ah3, c00, c01);
      mma16816(acc[0], al0, al1, al2, al3, b00, b01);
      mma16816(acc[1], ah0, ah1, ah2, ah3, b10, b11);
      mma16816(acc[1], ah0, ah1, ah2, ah3, c10, c11);
      mma16816(acc[1], al0, al1, al2, al3, b10, b11);
    }
    __syncthreads();
  }

  const int q  = lane & 3;
  const int r8 = lane >> 2;
  size_t base = ((size_t)b*192 + outBase)*HW;
  #pragma unroll
  for (int nfi = 0; nfi < 2; nfi++){
    int nf = nf0 + nfi*4;
    #pragma unroll
    for (int e = 0; e < 4; e++){
      int oc = nf*8 + 2*q + (e & 1);
      int pix = p0 + mf*16 + r8 + (e >> 1)*8;
      out[base + (size_t)oc*HW + pix] = acc[nfi][e];
    }
  }
}

__global__ void dcn_all(const float* __restrict__ xt,
                        const float* __restrict__ y3, const float* __restrict__ y5,
                        const float* __restrict__ y7a, const float* __restrict__ y7b,
                        const float* __restrict__ bp7,
                        const __nv_bfloat16* __restrict__ wdb3, const __nv_bfloat16* __restrict__ wdb5,
                        const __nv_bfloat16* __restrict__ wdb7,
                        float* __restrict__ out){
  extern __shared__ __align__(16) char smem[];
  int blk = blockIdx.x;
  if (blk < 400)      dcn_branch<7,true> (smem, xt, y7a, y7b, bp7, wdb7, out, 128, blk);
  else if (blk < 800) dcn_branch<5,false>(smem, xt, y5, (const float*)0, (const float*)0, wdb5, out, 64,  blk - 400);
  else                dcn_branch<3,false>(smem, xt, y3, (const float*)0, (const float*)0, wdb3, out, 0,   blk - 800);
}

// ---------------- launch ----------------
extern "C" void kernel_launch(void* const* d_in, const int* in_sizes, int n_in,
                              void* d_out, int out_size){
  const float* x       = (const float*)d_in[0];
  const float* w_off3  = (const float*)d_in[1];
  const float* b_off3  = (const float*)d_in[2];
  const float* w_mask3 = (const float*)d_in[3];
  const float* b_mask3 = (const float*)d_in[4];
  const float* w_dcn3  = (const float*)d_in[5];
  const float* w_off5  = (const float*)d_in[6];
  const float* b_off5  = (const float*)d_in[7];
  const float* w_mask5 = (const float*)d_in[8];
  const float* b_mask5 = (const float*)d_in[9];
  const float* w_dcn5  = (const float*)d_in[10];
  const float* w_off7  = (const float*)d_in[11];
  const float* b_off7  = (const float*)d_in[12];
  const float* w_mask7 = (const float*)d_in[13];
  const float* b_mask7 = (const float*)d_in[14];
  const float* w_dcn7  = (const float*)d_in[15];
  float* out = (float*)d_out;

  float *xt, *y3, *y5, *y7a, *y7b, *b3, *b5, *b7;
  __nv_bfloat16 *xhi, *xlo, *gw3, *gw5, *gw7, *wdb3, *wdb5, *wdb7;
  cudaGetSymbolAddress((void**)&xt,  g_xt);
  cudaGetSymbolAddress((void**)&xhi, g_xhi);
  cudaGetSymbolAddress((void**)&xlo, g_xlo);
  cudaGetSymbolAddress((void**)&y3,  g_y3);
  cudaGetSymbolAddress((void**)&y5,  g_y5);
  cudaGetSymbolAddress((void**)&y7a, g_y7a);
  cudaGetSymbolAddress((void**)&y7b, g_y7b);
  cudaGetSymbolAddress((void**)&b3,  g_b3);
  cudaGetSymbolAddress((void**)&b5,  g_b5);
  cudaGetSymbolAddress((void**)&b7,  g_b7);
  cudaGetSymbolAddress((void**)&gw3, g_gw3);
  cudaGetSymbolAddress((void**)&gw5, g_gw5);
  cudaGetSymbolAddress((void**)&gw7, g_gw7);
  cudaGetSymbolAddress((void**)&wdb3, g_wdb3);
  cudaGetSymbolAddress((void**)&wdb5, g_wdb5);
  cudaGetSymbolAddress((void**)&wdb7, g_wdb7);

  const int smemConv = 2*14*22*144 + 2*152*144;   // 132480 (k7 worst case)
  const int smemDcn  = 4608*2 + 2*9216;           // 27648
  cudaFuncSetAttribute(conv_all, cudaFuncAttributeMaxDynamicSharedMemorySize, smemConv);
  cudaFuncSetAttribute(dcn_all,  cudaFuncAttributeMaxDynamicSharedMemorySize, smemDcn);

  transpose_kernel<<<400, 256>>>(x, xt, xhi, xlo);
  pack_all<<<256, 256>>>(w_off3, b_off3, w_mask3, b_mask3, w_dcn3,
                         w_off5, b_off5, w_mask5, b_mask5, w_dcn5,
                         w_off7, b_off7, w_mask7, b_mask7, w_dcn7,
                         gw3, b3, wdb3, gw5, b5, wdb5, gw7, b7, wdb7);

  conv_all<<<400, 256, smemConv>>>(xhi, xlo, gw3, gw5, gw7, b3, b5, b7, y3, y5, y7a, y7b);
  dcn_all<<<1200, 256, smemDcn>>>(xt, y3, y5, y7a, y7b, b7, wdb3, wdb5, wdb7, out);
}

// round 11
// speedup vs baseline: 1.3997x; 1.1720x over previous
#include <cuda_runtime.h>
#include <cuda_bf16.h>
#include <cuda_fp16.h>
#include <math.h>
#include <stdint.h>

#define B_   2
#define CIN  64
#define H_   80
#define W_   80
#define HW   6400
#define FULLM 0xFFFFFFFFu

// ---------------- mma.sync m16n8k16 (sm_80+ baseline) ----------------
__device__ __forceinline__ void mma16816(float* c, uint32_t a0, uint32_t a1, uint32_t a2, uint32_t a3,
                                         uint32_t b0, uint32_t b1){
  asm volatile("mma.sync.aligned.m16n8k16.row.col.f32.bf16.bf16.f32 "
    "{%0,%1,%2,%3}, {%4,%5,%6,%7}, {%8,%9}, {%0,%1,%2,%3};"
    : "+f"(c[0]), "+f"(c[1]), "+f"(c[2]), "+f"(c[3])
    : "r"(a0), "r"(a1), "r"(a2), "r"(a3), "r"(b0), "r"(b1));
}
__device__ __forceinline__ void mma16816h(float* c, uint32_t a0, uint32_t a1, uint32_t a2, uint32_t a3,
                                          uint32_t b0, uint32_t b1){
  asm volatile("mma.sync.aligned.m16n8k16.row.col.f32.f16.f16.f32 "
    "{%0,%1,%2,%3}, {%4,%5,%6,%7}, {%8,%9}, {%0,%1,%2,%3};"
    : "+f"(c[0]), "+f"(c[1]), "+f"(c[2]), "+f"(c[3])
    : "r"(a0), "r"(a1), "r"(a2), "r"(a3), "r"(b0), "r"(b1));
}
__device__ __forceinline__ void ldmx4(uint32_t& r0, uint32_t& r1, uint32_t& r2, uint32_t& r3, uint32_t addr){
  asm volatile("ldmatrix.sync.aligned.m8n8.x4.shared.b16 {%0,%1,%2,%3}, [%4];"
    : "=r"(r0), "=r"(r1), "=r"(r2), "=r"(r3) : "r"(addr));
}
__device__ __forceinline__ void ldmx2(uint32_t& r0, uint32_t& r1, uint32_t addr){
  asm volatile("ldmatrix.sync.aligned.m8n8.x2.shared.b16 {%0,%1}, [%2];"
    : "=r"(r0), "=r"(r1) : "r"(addr));
}

// ---------------- scratch ----------------
__device__ __align__(16) float g_xt[B_*HW*CIN];
__device__ __align__(16) __nv_bfloat16 g_xhi[B_*HW*CIN];
__device__ __align__(16) __nv_bfloat16 g_xlo[B_*HW*CIN];
__device__ float g_y3[B_*27*HW];
__device__ float g_y5[B_*75*HW];
__device__ float g_y7a[B_*147*HW];
__device__ float g_y7b[B_*147*HW];
__device__ float g_b3[32];
__device__ float g_b5[80];
__device__ float g_b7[152];
__device__ __align__(16) __nv_bfloat16 g_gw3[9*2*32*64];
__device__ __align__(16) __nv_bfloat16 g_gw5[25*2*80*64];
__device__ __align__(16) __nv_bfloat16 g_gw7[49*2*152*64];
// dcn weights fp16 single, [tap][64 oc][64 c]
__device__ __align__(16) __half g_wdh3[9*64*64];
__device__ __align__(16) __half g_wdh5[25*64*64];
__device__ __align__(16) __half g_wdh7[49*64*64];

// ---------------- NCHW -> NHWC transpose (+ bf16 hi/lo split) ----------------
__global__ void transpose_kernel(const float* __restrict__ x, float* __restrict__ xt,
                                 __nv_bfloat16* __restrict__ xhi, __nv_bfloat16* __restrict__ xlo){
  __shared__ float s[64][33];
  int b   = blockIdx.x / 200;
  int hw0 = (blockIdx.x % 200) * 32;
  int tx = threadIdx.x & 31, ty = threadIdx.x >> 5;
  #pragma unroll
  for (int i = 0; i < 8; i++){
    int c = i*8 + ty;
    s[c][tx] = x[((size_t)(b*CIN + c))*HW + hw0 + tx];
  }
  __syncthreads();
  #pragma unroll
  for (int i = 0; i < 8; i++){
    int idx = i*256 + threadIdx.x;
    int hw = idx >> 6, c = idx & 63;
    float v = s[c][hw];
    size_t o = ((size_t)b*HW + hw0 + hw)*CIN + c;
    xt[o] = v;
    __nv_bfloat16 hi = __float2bfloat16(v);
    xhi[o] = hi;
    xlo[o] = __float2bfloat16(v - __bfloat162float(hi));
  }
}

// ---------------- merged weight packing ----------------
template<int KK, int NP>
__device__ __forceinline__ void pack_branch(const float* __restrict__ woff, const float* __restrict__ boff,
                            const float* __restrict__ wmask, const float* __restrict__ bmask,
                            const float* __restrict__ wdcn,
                            __nv_bfloat16* __restrict__ gw, float* __restrict__ bp,
                            __half* __restrict__ wdh){
  int stride = gridDim.x * blockDim.x;
  int t0 = blockIdx.x*blockDim.x + threadIdx.x;
  for (int i = t0; i < KK*2*NP*64; i += stride){
    int tap = i / (2*NP*64);
    int s   = (i / (NP*64)) & 1;
    int n   = (i / 64) % NP;
    int c   = i & 63;
    float v = 0.f;
    if (n < 2*KK)      v = woff[((size_t)n*CIN + c)*KK + tap];
    else if (n < 3*KK) v = wmask[((size_t)(n-2*KK)*CIN + c)*KK + tap];
    __nv_bfloat16 hi = __float2bfloat16(v);
    gw[i] = (s == 0) ? hi : __float2bfloat16(v - __bfloat162float(hi));
  }
  for (int i = t0; i < NP; i += stride){
    float v = 0.f;
    if (i < 2*KK)      v = boff[i];
    else if (i < 3*KK) v = bmask[i-2*KK];
    bp[i] = v;
  }
  for (int i = t0; i < KK*4096; i += stride){
    int tap = i / 4096;
    int n   = (i >> 6) & 63;
    int c   = i & 63;
    wdh[i] = __float2half(wdcn[((size_t)n*64 + c)*KK + tap]);
  }
}

__global__ void pack_all(const float* w_off3, const float* b_off3, const float* w_mask3, const float* b_mask3, const float* w_dcn3,
                         const float* w_off5, const float* b_off5, const float* w_mask5, const float* b_mask5, const float* w_dcn5,
                         const float* w_off7, const float* b_off7, const float* w_mask7, const float* b_mask7, const float* w_dcn7,
                         __nv_bfloat16* gw3, float* bp3, __half* wdh3,
                         __nv_bfloat16* gw5, float* bp5, __half* wdh5,
                         __nv_bfloat16* gw7, float* bp7, __half* wdh7){
  pack_branch<49,152>(w_off7, b_off7, w_mask7, b_mask7, w_dcn7, gw7, bp7, wdh7);
  pack_branch<25,80> (w_off5, b_off5, w_mask5, b_mask5, w_dcn5, gw5, bp5, wdh5);
  pack_branch<9,32>  (w_off3, b_off3, w_mask3, b_mask3, w_dcn3, gw3, bp3, wdh3);
}

// ---------------- HMMA implicit-GEMM conv branch (tap range, optional epilogue) ----------------
template<int K, int NP, bool EPI>
__device__ __forceinline__ void conv_branch(char* smem,
                         const __nv_bfloat16* __restrict__ xhi, const __nv_bfloat16* __restrict__ xlo,
                         const __nv_bfloat16* __restrict__ gw, const float* __restrict__ bp,
                         float* __restrict__ y, int blk, int tap0, int tapN){
  constexpr int KK = K*K, PAD = K/2, Cout = 3*KK, NF = NP/8;
  constexpr int HR = 8 + K - 1, WR = 16 + K - 1;
  constexpr int PITCH = 144;
  constexpr int XS_SPLIT = HR*WR*PITCH;
  constexpr int BS_OFF   = 2*XS_SPLIT;
  constexpr int BS_SPLIT = NP*PITCH;

  char* xs = smem;
  char* Bs = smem + BS_OFF;

  const int tid  = threadIdx.x;
  const int warp = tid >> 5;
  const int lane = tid & 31;
  const int b = blk / 50;
  const int t = blk % 50;
  const int ty0 = (t / 5) * 8;
  const int tx0 = (t % 5) * 16;

  for (int i = tid; i < HR*WR*8; i += 256){
    int hp = i >> 3, c16 = i & 7;
    int gy = ty0 - PAD + hp / WR;
    int gx = tx0 - PAD + hp % WR;
    uint4 vh = make_uint4(0,0,0,0), vl = make_uint4(0,0,0,0);
    if (gy >= 0 && gy < H_ && gx >= 0 && gx < W_){
      size_t idx = ((size_t)(b*HW + gy*W_ + gx))*64 + c16*8;
      vh = *(const uint4*)(xhi + idx);
      vl = *(const uint4*)(xlo + idx);
    }
    *(uint4*)(xs + hp*PITCH + c16*16) = vh;
    *(uint4*)(xs + XS_SPLIT + hp*PITCH + c16*16) = vl;
  }

  float acc[NF][4];
  #pragma unroll
  for (int nf = 0; nf < NF; nf++){
    acc[nf][0] = acc[nf][1] = acc[nf][2] = acc[nf][3] = 0.f;
  }

  const int q  = lane & 3;
  const int r8 = lane >> 2;

  for (int tap = tap0; tap < tapN; tap++){
    for (int i = tid; i < 2*NP*8; i += 256){
      int s = i / (NP*8);
      int n = (i >> 3) % NP;
      int c16 = i & 7;
      uint4 v = *(const uint4*)(gw + (((size_t)tap*2 + s)*NP + n)*64 + c16*8);
      *(uint4*)(Bs + s*BS_SPLIT + n*PITCH + c16*16) = v;
    }
    __syncthreads();

    int iy = tap / K, ix = tap % K;
    const char* abase = xs + ((warp + iy)*WR + ix + r8)*PITCH + q*4;

    #pragma unroll
    for (int ks = 0; ks < 4; ks++){
      uint32_t ah0 = *(const uint32_t*)(abase + ks*32);
      uint32_t ah1 = *(const uint32_t*)(abase + 8*PITCH + ks*32);
      uint32_t ah2 = *(const uint32_t*)(abase + ks*32 + 16);
      uint32_t ah3 = *(const uint32_t*)(abase + 8*PITCH + ks*32 + 16);
      uint32_t al0 = *(const uint32_t*)(abase + XS_SPLIT + ks*32);
      uint32_t al1 = *(const uint32_t*)(abase + XS_SPLIT + 8*PITCH + ks*32);
      uint32_t al2 = *(const uint32_t*)(abase + XS_SPLIT + ks*32 + 16);
      uint32_t al3 = *(const uint32_t*)(abase + XS_SPLIT + 8*PITCH + ks*32 + 16);
      #pragma unroll
      for (int nf = 0; nf < NF; nf++){
        const char* bbase = Bs + (nf*8 + r8)*PITCH + q*4 + ks*32;
        uint32_t bh0 = *(const uint32_t*)(bbase);
        uint32_t bh1 = *(const uint32_t*)(bbase + 16);
        uint32_t bl0 = *(const uint32_t*)(bbase + BS_SPLIT);
        uint32_t bl1 = *(const uint32_t*)(bbase + BS_SPLIT + 16);
        mma16816(acc[nf], ah0, ah1, ah2, ah3, bh0, bh1);
        mma16816(acc[nf], ah0, ah1, ah2, ah3, bl0, bl1);
        mma16816(acc[nf], al0, al1, al2, al3, bh0, bh1);
      }
    }
    __syncthreads();
  }

  const int h = ty0 + warp;
  const int col0 = (lane & 3)*2;
  #pragma unroll
  for (int nf = 0; nf < NF; nf++){
    #pragma unroll
    for (int e = 0; e < 4; e++){
      int oc = nf*8 + col0 + (e & 1);
      int pc = r8 + (e >> 1)*8;
      if (oc < Cout){
        float v = acc[nf][e];
        if (EPI){
          v += __ldg(bp + oc);
          if (oc >= 2*KK) v = 1.f/(1.f + __expf(-v));
        }
        y[((size_t)(b*Cout + oc))*HW + h*W_ + tx0 + pc] = v;
      }
    }
  }
}

// merged conv: 400 blocks (k7 split into two tap halves, raw partials)
__global__ void conv_all(const __nv_bfloat16* __restrict__ xhi, const __nv_bfloat16* __restrict__ xlo,
                         const __nv_bfloat16* __restrict__ gw3, const __nv_bfloat16* __restrict__ gw5,
                         const __nv_bfloat16* __restrict__ gw7,
                         const float* __restrict__ b3, const float* __restrict__ b5, const float* __restrict__ b7,
                         float* __restrict__ y3, float* __restrict__ y5,
                         float* __restrict__ y7a, float* __restrict__ y7b){
  extern __shared__ __align__(16) char smem[];
  int blk = blockIdx.x;
  if (blk < 100)       conv_branch<7,152,false>(smem, xhi, xlo, gw7, b7, y7a, blk,       0, 25);
  else if (blk < 200)  conv_branch<7,152,false>(smem, xhi, xlo, gw7, b7, y7b, blk - 100, 25, 49);
  else if (blk < 300)  conv_branch<5,80,true>  (smem, xhi, xlo, gw5, b5, y5,  blk - 200, 0, 25);
  else                 conv_branch<3,32,true>  (smem, xhi, xlo, gw3, b3, y3,  blk - 300, 0, 9);
}

// ---------------- fp16 HMMA deformable sampling + DCN (32 px/CTA) ----------------
// smem: sampH[32][144]=4608, Bs[64][144]=9216 -> 13824
template<int K, bool MERGE>
__device__ __forceinline__ void dcn_branch(char* smem,
                          const float* __restrict__ xt,
                          const float* __restrict__ offm, const float* __restrict__ offm2,
                          const float* __restrict__ bp,
                          const __half* __restrict__ wdh, float* __restrict__ out,
                          int outBase, int blk){
  constexpr int KK = K*K, PAD = K/2, C3 = 3*KK;
  constexpr int PITCH = 144;
  char* sampH = smem;
  char* Bs    = smem + 4608;

  const int tid  = threadIdx.x;
  const int warp = tid >> 5;
  const int lane = tid & 31;
  const int b  = blk / 200;
  const int p0 = (blk % 200) * 32;
  const int mf = warp & 1;
  const int nf0 = warp >> 1;
  const float* xb    = xt + (size_t)b*HW*CIN;
  const float* offb  = offm + (size_t)b*C3*HW;
  const float* offb2 = MERGE ? (offm2 + (size_t)b*C3*HW) : (const float*)0;

  const int pr    = lane & 3;
  const int mypix = p0 + warp*4 + pr;
  const int myh   = mypix / W_;
  const int myw   = mypix - myh*W_;
  const int pg = lane >> 4;
  const int cq = (lane & 15) * 4;

  const uint32_t sBaseH = (uint32_t)__cvta_generic_to_shared(sampH);
  const uint32_t sBaseB = (uint32_t)__cvta_generic_to_shared(Bs);
  const uint32_t aH = sBaseH + (mf*16 + (lane & 15))*PITCH + ((lane >> 4) << 4);
  const uint32_t bRowOff = (lane & 7)*PITCH + (((lane >> 3) & 1) << 4);
  const uint32_t bH0 = sBaseB + (nf0*8)*PITCH + bRowOff;
  const uint32_t bH1 = bH0 + 32*PITCH;

  float acc[2][4];
  acc[0][0]=acc[0][1]=acc[0][2]=acc[0][3]=0.f;
  acc[1][0]=acc[1][1]=acc[1][2]=acc[1][3]=0.f;

  for (int j = 0; j < KK; j++){
    // stage fp16 dcn weights for this tap (8KB)
    for (int i = tid; i < 512; i += 256){
      int n = i >> 3, c16 = i & 7;
      uint4 v = *(const uint4*)(wdh + (size_t)j*4096 + n*64 + c16*8);
      *(uint4*)(Bs + n*PITCH + c16*16) = v;
    }
    // ---- coefficients (lane-parallel, one pixel per lane) ----
    int iy = j / K, ix = j - iy*K;
    float oy = __ldg(offb + (size_t)(2*j)*HW + mypix);
    float ox = __ldg(offb + (size_t)(2*j + 1)*HW + mypix);
    float m  = __ldg(offb + (size_t)(2*KK + j)*HW + mypix);
    if (MERGE){
      oy += __ldg(offb2 + (size_t)(2*j)*HW + mypix)     + __ldg(bp + 2*j);
      ox += __ldg(offb2 + (size_t)(2*j + 1)*HW + mypix) + __ldg(bp + 2*j + 1);
      m  += __ldg(offb2 + (size_t)(2*KK + j)*HW + mypix) + __ldg(bp + 2*KK + j);
      m = 1.f/(1.f + __expf(-m));
    }
    float py = (float)(myh - PAD + iy) + oy;
    float px = (float)(myw - PAD + ix) + ox;
    float y0f = floorf(py), x0f = floorf(px);
    float wy1 = py - y0f, wx1 = px - x0f;
    float wy0 = 1.f - wy1, wx0 = 1.f - wx1;
    int y0 = (int)y0f, x0 = (int)x0f;
    bool vy0 = (y0 >= 0)  && (y0 < H_);
    bool vy1 = (y0 >= -1) && (y0 < H_ - 1);
    bool vx0 = (x0 >= 0)  && (x0 < W_);
    bool vx1 = (x0 >= -1) && (x0 < W_ - 1);
    float w00 = (vy0 && vx0) ? wy0*wx0*m : 0.f;
    float w01 = (vy0 && vx1) ? wy0*wx1*m : 0.f;
    float w10 = (vy1 && vx0) ? wy1*wx0*m : 0.f;
    float w11 = (vy1 && vx1) ? wy1*wx1*m : 0.f;
    int y0c = min(max(y0, 0), H_-1), y1c = min(max(y0 + 1, 0), H_-1);
    int x0c = min(max(x0, 0), W_-1), x1c = min(max(x0 + 1, 0), W_-1);
    int o00 = y0c*W_ + x0c, o01 = y0c*W_ + x1c;
    int o10 = y1c*W_ + x0c, o11 = y1c*W_ + x1c;

    // ---- gather: 2 rounds x 2 pixels, float4 per lane ----
    #pragma unroll
    for (int r = 0; r < 2; r++){
      int p = r*2 + pg;
      float W00 = __shfl_sync(FULLM, w00, p);
      float W01 = __shfl_sync(FULLM, w01, p);
      float W10 = __shfl_sync(FULLM, w10, p);
      float W11 = __shfl_sync(FULLM, w11, p);
      int O00 = __shfl_sync(FULLM, o00, p);
      int O01 = __shfl_sync(FULLM, o01, p);
      int O10 = __shfl_sync(FULLM, o10, p);
      int O11 = __shfl_sync(FULLM, o11, p);
      float4 t00 = *(const float4*)(xb + (size_t)O00*CIN + cq);
      float4 t01 = *(const float4*)(xb + (size_t)O01*CIN + cq);
      float4 t10 = *(const float4*)(xb + (size_t)O10*CIN + cq);
      float4 t11 = *(const float4*)(xb + (size_t)O11*CIN + cq);
      float v0 = W00*t00.x + W01*t01.x + W10*t10.x + W11*t11.x;
      float v1 = W00*t00.y + W01*t01.y + W10*t10.y + W11*t11.y;
      float v2 = W00*t00.z + W01*t01.z + W10*t10.z + W11*t11.z;
      float v3 = W00*t00.w + W01*t01.w + W10*t10.w + W11*t11.w;
      __half2 hv01 = __floats2half2_rn(v0, v1);
      __half2 hv23 = __floats2half2_rn(v2, v3);
      uint2 hv;
      hv.x = *(uint32_t*)&hv01;
      hv.y = *(uint32_t*)&hv23;
      int pp = warp*4 + p;
      *(uint2*)(sampH + pp*PITCH + (lane & 15)*8) = hv;
    }
    __syncthreads();
    // ---- single fp16 mma pass ----
    #pragma unroll
    for (int ks = 0; ks < 4; ks++){
      uint32_t a0, a1, a2, a3;
      ldmx4(a0, a1, a2, a3, aH + ks*32);
      uint32_t b00, b01, b10, b11;
      ldmx2(b00, b01, bH0 + ks*32);
      ldmx2(b10, b11, bH1 + ks*32);
      mma16816h(acc[0], a0, a1, a2, a3, b00, b01);
      mma16816h(acc[1], a0, a1, a2, a3, b10, b11);
    }
    __syncthreads();
  }

  const int q  = lane & 3;
  const int r8 = lane >> 2;
  size_t base = ((size_t)b*192 + outBase)*HW;
  #pragma unroll
  for (int nfi = 0; nfi < 2; nfi++){
    int nf = nf0 + nfi*4;
    #pragma unroll
    for (int e = 0; e < 4; e++){
      int oc = nf*8 + 2*q + (e & 1);
      int pix = p0 + mf*16 + r8 + (e >> 1)*8;
      out[base + (size_t)oc*HW + pix] = acc[nfi][e];
    }
  }
}

__global__ void dcn_all(const float* __restrict__ xt,
                        const float* __restrict__ y3, const float* __restrict__ y5,
                        const float* __restrict__ y7a, const float* __restrict__ y7b,
                        const float* __restrict__ bp7,
                        const __half* __restrict__ wdh3, const __half* __restrict__ wdh5,
                        const __half* __restrict__ wdh7,
                        float* __restrict__ out){
  extern __shared__ __align__(16) char smem[];
  int blk = blockIdx.x;
  if (blk < 400)      dcn_branch<7,true> (smem, xt, y7a, y7b, bp7, wdh7, out, 128, blk);
  else if (blk < 800) dcn_branch<5,false>(smem, xt, y5, (const float*)0, (const float*)0, wdh5, out, 64,  blk - 400);
  else                dcn_branch<3,false>(smem, xt, y3, (const float*)0, (const float*)0, wdh3, out, 0,   blk - 800);
}

// ---------------- launch ----------------
extern "C" void kernel_launch(void* const* d_in, const int* in_sizes, int n_in,
                              void* d_out, int out_size){
  const float* x       = (const float*)d_in[0];
  const float* w_off3  = (const float*)d_in[1];
  const float* b_off3  = (const float*)d_in[2];
  const float* w_mask3 = (const float*)d_in[3];
  const float* b_mask3 = (const float*)d_in[4];
  const float* w_dcn3  = (const float*)d_in[5];
  const float* w_off5  = (const float*)d_in[6];
  const float* b_off5  = (const float*)d_in[7];
  const float* w_mask5 = (const float*)d_in[8];
  const float* b_mask5 = (const float*)d_in[9];
  const float* w_dcn5  = (const float*)d_in[10];
  const float* w_off7  = (const float*)d_in[11];
  const float* b_off7  = (const float*)d_in[12];
  const float* w_mask7 = (const float*)d_in[13];
  const float* b_mask7 = (const float*)d_in[14];
  const float* w_dcn7  = (const float*)d_in[15];
  float* out = (float*)d_out;

  float *xt, *y3, *y5, *y7a, *y7b, *b3, *b5, *b7;
  __nv_bfloat16 *xhi, *xlo, *gw3, *gw5, *gw7;
  __half *wdh3, *wdh5, *wdh7;
  cudaGetSymbolAddress((void**)&xt,  g_xt);
  cudaGetSymbolAddress((void**)&xhi, g_xhi);
  cudaGetSymbolAddress((void**)&xlo, g_xlo);
  cudaGetSymbolAddress((void**)&y3,  g_y3);
  cudaGetSymbolAddress((void**)&y5,  g_y5);
  cudaGetSymbolAddress((void**)&y7a, g_y7a);
  cudaGetSymbolAddress((void**)&y7b, g_y7b);
  cudaGetSymbolAddress((void**)&b3,  g_b3);
  cudaGetSymbolAddress((void**)&b5,  g_b5);
  cudaGetSymbolAddress((void**)&b7,  g_b7);
  cudaGetSymbolAddress((void**)&gw3, g_gw3);
  cudaGetSymbolAddress((void**)&gw5, g_gw5);
  cudaGetSymbolAddress((void**)&gw7, g_gw7);
  cudaGetSymbolAddress((void**)&wdh3, g_wdh3);
  cudaGetSymbolAddress((void**)&wdh5, g_wdh5);
  cudaGetSymbolAddress((void**)&wdh7, g_wdh7);

  const int smemConv = 2*14*22*144 + 2*152*144;   // 132480 (k7 worst case)
  const int smemDcn  = 4608 + 9216;               // 13824
  cudaFuncSetAttribute(conv_all, cudaFuncAttributeMaxDynamicSharedMemorySize, smemConv);
  cudaFuncSetAttribute(dcn_all,  cudaFuncAttributeMaxDynamicSharedMemorySize, smemDcn);

  transpose_kernel<<<400, 256>>>(x, xt, xhi, xlo);
  pack_all<<<256, 256>>>(w_off3, b_off3, w_mask3, b_mask3, w_dcn3,
                         w_off5, b_off5, w_mask5, b_mask5, w_dcn5,
                         w_off7, b_off7, w_mask7, b_mask7, w_dcn7,
                         gw3, b3, wdh3, gw5, b5, wdh5, gw7, b7, wdh7);

  conv_all<<<400, 256, smemConv>>>(xhi, xlo, gw3, gw5, gw7, b3, b5, b7, y3, y5, y7a, y7b);
  dcn_all<<<1200, 256, smemDcn>>>(xt, y3, y5, y7a, y7b, b7, wdh3, wdh5, wdh7, out);
}